// round 1
// baseline (speedup 1.0000x reference)
#include <cuda_runtime.h>
#include <math.h>

// ISDALoss_EM on GB300.
// Inputs (metadata order): features[N,128] f32, weight[C,128] f32, bias[C] f32,
//   pi[C,K] f32 (UNUSED - see analysis), mu[C,K,128] f32, sigma[C,K,128,128] f32,
//   labels[N] int64-or-int32, ratio scalar f32.
// Output: [loss (1 elem), y (N*C elems)] f32.

#define A_DIM 128
#define MAX_S 512
#define MAX_N 4096

// ---------------- scratch (device globals; no allocations allowed) ----------
__device__ float g_LT[(size_t)MAX_S * A_DIM * A_DIM]; // LT[s][j][i] = L[i][j], zeros above diag
__device__ float g_rdiag[MAX_S * A_DIM];              // 1 / L[j][j]
__device__ float g_logdet[MAX_S];                     // log|Sigma_s|
__device__ float g_D[MAX_S * A_DIM];                  // D[s][c] = w_c^T Sigma_s w_c   (stride 128)
__device__ float g_U[MAX_S * A_DIM];                  // U[s][c] = w_c^T Sigma_s w_cl
__device__ int   g_labels[MAX_N];
__device__ int   g_kstar[MAX_N];

// ---------------- init loss slot --------------------------------------------
__global__ void k_init(float* out, int writeLoss) {
    if (writeLoss && threadIdx.x == 0 && blockIdx.x == 0) out[0] = 0.0f;
}

// ---------------- label dtype detection + conversion ------------------------
// If labels are int64, the odd int32 words (high halves) of the first N int32
// slots are all zero. If int32, they are random labels in [0,100) -> ~never all 0.
__global__ void k_labels(const int* __restrict__ raw, int n) {
    __shared__ int odd_nz;
    if (threadIdx.x == 0) odd_nz = 0;
    __syncthreads();
    for (int i = threadIdx.x; i < n / 2; i += blockDim.x)
        if (raw[2 * i + 1] != 0) atomicOr(&odd_nz, 1);
    __syncthreads();
    if (odd_nz == 0) {
        for (int i = threadIdx.x; i < n; i += blockDim.x) g_labels[i] = raw[2 * i];
    } else {
        for (int i = threadIdx.x; i < n; i += blockDim.x) g_labels[i] = raw[i];
    }
}

// ---------------- Cholesky of each Sigma_s (128x128, SPD) -------------------
// One block of 128 threads per sigma. In-shared right-looking factorization,
// pitch 129 to keep row accesses conflict-free.
__global__ void k_chol(const float* __restrict__ sigma) {
    extern __shared__ float sA[];            // 128 x 129
    __shared__ float scol[A_DIM];
    __shared__ float red[4];
    const int s = blockIdx.x;
    const int tid = threadIdx.x;             // 0..127
    const float* src = sigma + (size_t)s * A_DIM * A_DIM;

    for (int idx = tid; idx < A_DIM * A_DIM; idx += A_DIM) {
        int r = idx >> 7, c = idx & 127;
        sA[r * 129 + c] = src[idx];
    }
    __syncthreads();

    for (int j = 0; j < A_DIM; ++j) {
        if (tid == j) sA[j * 129 + j] = sqrtf(sA[j * 129 + j]);
        __syncthreads();
        float Ljj = sA[j * 129 + j];
        float inv = 1.0f / Ljj;
        float lij = 0.0f;
        if (tid > j) {
            lij = sA[tid * 129 + j] * inv;
            sA[tid * 129 + j] = lij;
        }
        scol[tid] = lij;
        __syncthreads();
        if (tid > j) {
            // rank-1 update of this thread's row, cols (j, tid]
            for (int p = j + 1; p <= tid; ++p)
                sA[tid * 129 + p] -= lij * scol[p];
        }
        __syncthreads();
    }

    // write L^T (column-major L) with zeros above the diagonal; coalesced
    for (int j = 0; j < A_DIM; ++j) {
        float v = (tid >= j) ? sA[tid * 129 + j] : 0.0f;
        g_LT[(size_t)s * (A_DIM * A_DIM) + j * A_DIM + tid] = v;
    }
    float dg = sA[tid * 129 + tid];
    g_rdiag[s * A_DIM + tid] = 1.0f / dg;

    float v = logf(dg);
    #pragma unroll
    for (int o = 16; o; o >>= 1) v += __shfl_xor_sync(0xffffffffu, v, o);
    if ((tid & 31) == 0) red[tid >> 5] = v;
    __syncthreads();
    if (tid == 0) g_logdet[s] = 2.0f * (red[0] + red[1] + red[2] + red[3]);
}

// ---------------- per-sigma D[s,c], U[s,c] precompute ------------------------
// Block per s (128 threads, thread = row a). v_i = Sigma_s @ w_{c0+i} computed
// for 4 columns at once; Sigma read transposed (symmetric) for conflict-free LDS.
__global__ void k_du(const float* __restrict__ sigma, const float* __restrict__ W,
                     int C, int K) {
    extern __shared__ float sS[];            // 128*128, sS[b*128+a] = Sigma[b][a]
    __shared__ float swl[A_DIM];
    __shared__ __align__(16) float swc[4][A_DIM];
    __shared__ float rbuf[4][8];
    const int s = blockIdx.x;
    const int tid = threadIdx.x;             // 0..127
    const int cl = s / K;
    const int a = tid;
    const int warp = tid >> 5, lane = tid & 31;
    const float* src = sigma + (size_t)s * A_DIM * A_DIM;

    for (int idx = tid; idx < A_DIM * A_DIM; idx += A_DIM) sS[idx] = src[idx];
    swl[tid] = W[cl * A_DIM + tid];
    __syncthreads();

    for (int c0 = 0; c0 < C; c0 += 4) {
        for (int idx = tid; idx < 4 * A_DIM; idx += A_DIM) {
            int ci = idx >> 7, b = idx & 127;
            int c = c0 + ci;
            swc[ci][b] = (c < C) ? W[c * A_DIM + b] : 0.0f;
        }
        __syncthreads();

        float acc0 = 0.f, acc1 = 0.f, acc2 = 0.f, acc3 = 0.f;
        #pragma unroll 8
        for (int b = 0; b < A_DIM; b += 4) {
            float4 w0 = *reinterpret_cast<const float4*>(&swc[0][b]);
            float4 w1 = *reinterpret_cast<const float4*>(&swc[1][b]);
            float4 w2 = *reinterpret_cast<const float4*>(&swc[2][b]);
            float4 w3 = *reinterpret_cast<const float4*>(&swc[3][b]);
            float sv0 = sS[(b + 0) * A_DIM + a];
            float sv1 = sS[(b + 1) * A_DIM + a];
            float sv2 = sS[(b + 2) * A_DIM + a];
            float sv3 = sS[(b + 3) * A_DIM + a];
            acc0 += sv0 * w0.x + sv1 * w0.y + sv2 * w0.z + sv3 * w0.w;
            acc1 += sv0 * w1.x + sv1 * w1.y + sv2 * w1.z + sv3 * w1.w;
            acc2 += sv0 * w2.x + sv1 * w2.y + sv2 * w2.z + sv3 * w2.w;
            acc3 += sv0 * w3.x + sv1 * w3.y + sv2 * w3.z + sv3 * w3.w;
        }
        // acc_i[a] = (Sigma w_{c0+i})[a]
        float wl = swl[a];
        float vals[8] = { acc0 * swc[0][a], acc1 * swc[1][a],
                          acc2 * swc[2][a], acc3 * swc[3][a],
                          acc0 * wl, acc1 * wl, acc2 * wl, acc3 * wl };
        #pragma unroll
        for (int v = 0; v < 8; ++v) {
            float x = vals[v];
            #pragma unroll
            for (int o = 16; o; o >>= 1) x += __shfl_xor_sync(0xffffffffu, x, o);
            if (lane == 0) rbuf[warp][v] = x;
        }
        __syncthreads();
        if (tid < 8) {
            float t = rbuf[0][tid] + rbuf[1][tid] + rbuf[2][tid] + rbuf[3][tid];
            int ci = tid & 3;
            int c = c0 + ci;
            if (c < C) {
                if (tid < 4) g_D[s * A_DIM + c] = t;
                else         g_U[s * A_DIM + c] = t;
            }
        }
        __syncthreads();
    }
}

// ---------------- expect: k*(n) = argmin_k (dist + logdet) ------------------
// One block per n, one warp per k. Forward solve L z = diff with lane r owning
// rows 4r..4r+3 (float4 coalesced column loads from L^T).
__global__ void k_expect(const float* __restrict__ F, const float* __restrict__ mu,
                         int N, int K) {
    const int n = blockIdx.x;
    const int warp = threadIdx.x >> 5, lane = threadIdx.x & 31;
    __shared__ float sscore[8];
    const int l = g_labels[n];

    if (warp < K) {
        const int s = l * K + warp;
        const float* LT = g_LT + (size_t)s * (A_DIM * A_DIM);
        const float* rd = g_rdiag + s * A_DIM;
        float4 fv = *reinterpret_cast<const float4*>(F + (size_t)n * A_DIM + 4 * lane);
        float4 mv = *reinterpret_cast<const float4*>(mu + (size_t)s * A_DIM + 4 * lane);
        float d0 = fv.x - mv.x, d1 = fv.y - mv.y, d2 = fv.z - mv.z, d3 = fv.w - mv.w;
        float dist = 0.0f;
        #pragma unroll 4
        for (int j = 0; j < A_DIM; ++j) {
            float4 col = make_float4(0.f, 0.f, 0.f, 0.f);
            if (4 * lane + 3 >= j)   // lower-triangle rows only (above-diag is 0 anyway)
                col = *reinterpret_cast<const float4*>(LT + j * A_DIM + 4 * lane);
            int owner = j >> 2, q = j & 3;
            float dq = (q == 0) ? d0 : (q == 1) ? d1 : (q == 2) ? d2 : d3;
            float dj = __shfl_sync(0xffffffffu, dq, owner);
            float zj = dj * rd[j];
            dist += zj * zj;
            d0 -= col.x * zj;
            d1 -= col.y * zj;
            d2 -= col.z * zj;
            d3 -= col.w * zj;
        }
        if (lane == 0) sscore[warp] = dist + g_logdet[s];
    }
    __syncthreads();
    if (threadIdx.x == 0) {
        float best = sscore[0];
        int bk = 0;
        for (int k = 1; k < K; ++k)
            if (sscore[k] < best) { best = sscore[k]; bk = k; }   // first-min tie-break
        g_kstar[n] = bk;
    }
}

// ---------------- fused y = F W^T + b, aug, log-softmax, loss ----------------
__global__ void k_yloss(const float* __restrict__ F, const float* __restrict__ W,
                        const float* __restrict__ bias, const float* __restrict__ ratioPtr,
                        float* __restrict__ yout, float* __restrict__ lossout,
                        int N, int C, int K, int writeLoss) {
    extern __shared__ float sh[];
    const int NB = 16;
    float* sWT = sh;                    // [128][C]  (W transposed)
    float* sF  = sWT + A_DIM * C;       // [NB][128]
    float* sY  = sF + NB * A_DIM;       // [NB][C]
    float* sB  = sY + NB * C;           // [C]
    const int tid = threadIdx.x;        // 256 threads
    const int n0 = blockIdx.x * NB;

    for (int idx = tid; idx < C * A_DIM; idx += 256) {
        int c = idx >> 7, aa = idx & 127;
        sWT[aa * C + c] = W[idx];
    }
    for (int idx = tid; idx < NB * A_DIM; idx += 256) {
        int nl = idx >> 7;
        int n = n0 + nl;
        sF[idx] = (n < N) ? F[(size_t)n * A_DIM + (idx & 127)] : 0.0f;
    }
    for (int c = tid; c < C; c += 256) sB[c] = bias[c];
    __syncthreads();

    const int warp = tid >> 5, lane = tid & 31;
    const int nchunk = (C + 31) >> 5;

    for (int task = warp; task < NB * nchunk; task += 8) {
        int nl = task / nchunk;
        int c = (task - nl * nchunk) * 32 + lane;
        int n = n0 + nl;
        if (c < C && n < N) {
            float acc = sB[c];
            const float* f = sF + nl * A_DIM;
            #pragma unroll 8
            for (int aa = 0; aa < A_DIM; ++aa) acc += f[aa] * sWT[aa * C + c];
            sY[nl * C + c] = acc;
            yout[(size_t)n * C + c] = acc;
        }
    }
    __syncthreads();

    const float hr = 0.5f * ratioPtr[0];
    for (int nl = warp; nl < NB; nl += 8) {
        int n = n0 + nl;
        if (n >= N) continue;
        int l = g_labels[n];
        int k = g_kstar[n];
        int s = l * K + k;
        const float* Dp = g_D + s * A_DIM;
        const float* Up = g_U + s * A_DIM;
        float ul = Up[l];
        float mymax = -INFINITY;
        float augv[8];
        for (int m = 0; m < nchunk; ++m) {
            int c = lane + 32 * m;
            float v = -INFINITY;
            if (c < C) v = sY[nl * C + c] + hr * (Dp[c] - 2.0f * Up[c] + ul);
            augv[m] = v;
            mymax = fmaxf(mymax, v);
        }
        #pragma unroll
        for (int o = 16; o; o >>= 1) mymax = fmaxf(mymax, __shfl_xor_sync(0xffffffffu, mymax, o));
        float sum = 0.0f;
        for (int m = 0; m < nchunk; ++m) {
            int c = lane + 32 * m;
            if (c < C) sum += expf(augv[m] - mymax);
        }
        #pragma unroll
        for (int o = 16; o; o >>= 1) sum += __shfl_xor_sync(0xffffffffu, sum, o);
        if (lane == 0 && writeLoss) {
            float lse = mymax + logf(sum);
            float aug_l = sY[nl * C + l] + hr * (Dp[l] - Up[l]); // -2u_l + u_l = -u_l
            atomicAdd(lossout, (lse - aug_l) / (float)N);
        }
    }
}

// ---------------- launch -----------------------------------------------------
extern "C" void kernel_launch(void* const* d_in, const int* in_sizes, int n_in,
                              void* d_out, int out_size) {
    const float* F      = (const float*)d_in[0];
    const float* W      = (const float*)d_in[1];
    const float* bias   = (const float*)d_in[2];
    /* d_in[3] = pi : unused (argmax(q) == argmax(log_p)) */
    const float* mu     = (const float*)d_in[4];
    const float* sigma  = (const float*)d_in[5];
    const int*   lraw   = (const int*)d_in[6];
    const float* ratio  = (const float*)d_in[7];

    const int C = in_sizes[2];                 // 100
    const int K = in_sizes[3] / C;             // 4
    const int Ad = in_sizes[1] / C;            // 128 (design assumes 128)
    const int N = in_sizes[0] / Ad;            // 2048
    const int S = C * K;                       // 400

    float* out = (float*)d_out;
    const int yoff = out_size - N * C;         // expected 1 (loss slot first)
    const int writeLoss = (yoff >= 1) ? 1 : 0;
    float* yout = out + (yoff > 0 ? yoff : 0);

    const int smem_chol = A_DIM * 129 * 4;                     // 66048
    const int smem_du   = A_DIM * A_DIM * 4;                   // 65536
    const int smem_yl   = (A_DIM * C + 16 * A_DIM + 16 * C + C) * 4;

    cudaFuncSetAttribute(k_chol,  cudaFuncAttributeMaxDynamicSharedMemorySize, smem_chol);
    cudaFuncSetAttribute(k_du,    cudaFuncAttributeMaxDynamicSharedMemorySize, smem_du);
    cudaFuncSetAttribute(k_yloss, cudaFuncAttributeMaxDynamicSharedMemorySize, smem_yl);

    k_init<<<1, 32>>>(out, writeLoss);
    k_labels<<<1, 256>>>(lraw, N);
    k_chol<<<S, A_DIM, smem_chol>>>(sigma);
    k_du<<<S, A_DIM, smem_du>>>(sigma, W, C, K);
    k_expect<<<N, 32 * K>>>(F, mu, N, K);
    k_yloss<<<(N + 15) / 16, 256, smem_yl>>>(F, W, bias, ratio, yout, out, N, C, K, writeLoss);
}